// round 9
// baseline (speedup 1.0000x reference)
#include <cuda_runtime.h>

// EfficientGCN preprocess on GB300 — smem-tiled, STG.128 paired-joint version.
// x: (N=128, C=3, T=300, V=25, M=2) fp32, conn: int32[25]
// out: (N, 3, 6, T, V, M) fp32
//
// Block = one (n, 20-row t-tile). Stage 3ch x 22rows x 50 floats (13.2KB).
// Output slabs: a 2-row segment (100 floats, even-t base) = 25 aligned float4.
// 250 threads each own one float4 column (= 2 adjacent joints, possibly
// straddling the row boundary — uniform code, no divergence) across all
// 18 slabs -> 18 STG.128 per thread instead of 36 STG.64.

#define N_ 128
#define C_ 3
#define T_ 300
#define V_ 25
#define RPT 20            // t-rows computed per tile
#define TILE_ROWS 22      // RPT + 2 halo
#define TILES_PER_N 15    // 300 / 20
#define ROWF 50           // floats per t-row (V*M)
#define CSLAB 15000       // floats per channel slab (T*ROWF)
#define SM_CH 1100        // floats per channel in smem (TILE_ROWS*ROWF)

struct JointRes {
    float2 a[3], xc[3], d1[3], d2[3], bv[3], ang[3];
};

__device__ __forceinline__ void compute_joint(
    const float* __restrict__ sm, const int* __restrict__ conn,
    int r, int v, int t, JointRes& o)
{
    const int pv = __ldg(&conn[v]);
    const float sel = (t < T_ - 2) ? 1.0f : 0.0f;

#pragma unroll
    for (int c = 0; c < C_; ++c) {
        const float* base = sm + c * SM_CH + r * ROWF;
        float2 a   = ((const float2*)base)[v];
        float2 cen = ((const float2*)base)[1];
        float2 par = ((const float2*)base)[pv];
        float2 n1  = ((const float2*)(base + ROWF))[v];
        float2 n2  = ((const float2*)(base + 2 * ROWF))[v];
        o.a[c]  = a;
        o.xc[c] = make_float2(a.x - cen.x, a.y - cen.y);
        o.d1[c] = make_float2((n1.x - a.x) * sel, (n1.y - a.y) * sel);
        o.d2[c] = make_float2((n2.x - a.x) * sel, (n2.y - a.y) * sel);
        o.bv[c] = make_float2(a.x - par.x, a.y - par.y);
    }

    float lx = sqrtf(o.bv[0].x * o.bv[0].x + o.bv[1].x * o.bv[1].x + o.bv[2].x * o.bv[2].x) + 1e-4f;
    float ly = sqrtf(o.bv[0].y * o.bv[0].y + o.bv[1].y * o.bv[1].y + o.bv[2].y * o.bv[2].y) + 1e-4f;
    float rlx = 1.0f / lx;
    float rly = 1.0f / ly;

#pragma unroll
    for (int c = 0; c < C_; ++c) {
        o.ang[c].x = acosf(o.bv[c].x * rlx);
        o.ang[c].y = acosf(o.bv[c].y * rly);
    }
}

__device__ __forceinline__ float4 pack4(const float2 a, const float2 b)
{
    return make_float4(a.x, a.y, b.x, b.y);
}

__global__ __launch_bounds__(256) void egcn_preprocess_v5(
    const float* __restrict__ x,
    const int* __restrict__ conn,
    float* __restrict__ out)
{
    __shared__ float sm[C_ * SM_CH];          // 3300 floats = 13.2 KB

    const int tid  = threadIdx.x;
    const int n    = blockIdx.x / TILES_PER_N;
    const int tile = blockIdx.x % TILES_PER_N;
    const int t0   = tile * RPT;

    const float* xn = x + n * (C_ * CSLAB);

    // ---- stage tile: 3 x 1100 floats = 825 float4 ----
    if (t0 + TILE_ROWS <= T_) {
        #pragma unroll
        for (int k = 0; k < 4; ++k) {
            int idx = tid + k * 256;
            if (idx < 825) {
                int c   = idx / 275;
                int rem = idx - c * 275;
                const float4* src = (const float4*)(xn + c * CSLAB + t0 * ROWF);
                ((float4*)(sm + c * SM_CH))[rem] = src[rem];
            }
        }
    } else {
        // last tile (t0=280): clamp halo rows 300,301 -> 299
        for (int idx = tid; idx < C_ * TILE_ROWS * V_; idx += 256) {
            int c   = idx / (TILE_ROWS * V_);
            int rem = idx - c * (TILE_ROWS * V_);
            int r   = rem / V_;
            int v   = rem - r * V_;
            int gt  = t0 + r; if (gt > T_ - 1) gt = T_ - 1;
            ((float2*)(sm + c * SM_CH + r * ROWF))[v] =
                ((const float2*)(xn + c * CSLAB + gt * ROWF))[v];
        }
    }
    __syncthreads();

    if (tid >= 250) return;

    const int rp = tid / 25;                  // row-pair 0..9
    const int k  = tid - rp * 25;             // float4 column 0..24

    // joints j0=2k, j1=2k+1 within the 50-joint row-pair segment
    const int j0 = 2 * k;
    const int j1 = 2 * k + 1;
    const int rA = 2 * rp + (j0 >= V_);
    const int vA = j0 - V_ * (j0 >= V_);
    const int rB = 2 * rp + (j1 >= V_);
    const int vB = j1 - V_ * (j1 >= V_);

    JointRes A, B;
    compute_joint(sm, conn, rA, vA, t0 + rA, A);
    compute_joint(sm, conn, rB, vB, t0 + rB, B);

    // ---- 18 streaming STG.128 ----
    float* ob = out + (size_t)n * 18 * CSLAB + (t0 + 2 * rp) * ROWF + 4 * k;

#pragma unroll
    for (int c = 0; c < C_; ++c) {
        __stcs((float4*)(ob + (c     ) * CSLAB), pack4(A.a[c],   B.a[c]));   // joint: x
        __stcs((float4*)(ob + (c + 3 ) * CSLAB), pack4(A.xc[c],  B.xc[c]));  // x - center
        __stcs((float4*)(ob + (c + 6 ) * CSLAB), pack4(A.d1[c],  B.d1[c]));  // v1
        __stcs((float4*)(ob + (c + 9 ) * CSLAB), pack4(A.d2[c],  B.d2[c]));  // v2
        __stcs((float4*)(ob + (c + 12) * CSLAB), pack4(A.bv[c],  B.bv[c]));  // bone vec
        __stcs((float4*)(ob + (c + 15) * CSLAB), pack4(A.ang[c], B.ang[c])); // bone angle
    }
}

extern "C" void kernel_launch(void* const* d_in, const int* in_sizes, int n_in,
                              void* d_out, int out_size)
{
    const float* x  = (const float*)d_in[0];
    const int* conn = (const int*)d_in[1];
    float* out      = (float*)d_out;

    const int blocks = N_ * TILES_PER_N;     // 1920
    egcn_preprocess_v5<<<blocks, 256>>>(x, conn, out);
}

// round 11
// speedup vs baseline: 1.2102x; 1.2102x over previous
#include <cuda_runtime.h>

// EfficientGCN preprocess on GB300 — smem-tiled, STG.128 paired joints,
// register-lean streaming variant (slabs stored immediately per channel;
// only bone vectors stay live across channels).
//
// x: (N=128, C=3, T=300, V=25, M=2) fp32, conn: int32[25]
// out: (N, 3, 6, T, V, M) fp32

#define N_ 128
#define C_ 3
#define T_ 300
#define V_ 25
#define RPT 20            // t-rows computed per tile
#define TILE_ROWS 22      // RPT + 2 halo
#define TILES_PER_N 15    // 300 / 20
#define ROWF 50           // floats per t-row (V*M)
#define CSLAB 15000       // floats per channel slab (T*ROWF)
#define SM_CH 1100        // floats per channel in smem (TILE_ROWS*ROWF)

__device__ __forceinline__ float4 pack4(const float2 a, const float2 b)
{
    return make_float4(a.x, a.y, b.x, b.y);
}

__global__ __launch_bounds__(256, 5) void egcn_preprocess_v6(
    const float* __restrict__ x,
    const int* __restrict__ conn,
    float* __restrict__ out)
{
    __shared__ float sm[C_ * SM_CH];          // 3300 floats = 13.2 KB

    const int tid  = threadIdx.x;
    const int n    = blockIdx.x / TILES_PER_N;
    const int tile = blockIdx.x % TILES_PER_N;
    const int t0   = tile * RPT;

    const float* xn = x + n * (C_ * CSLAB);

    // ---- stage tile: 3 x 1100 floats = 825 float4 ----
    if (t0 + TILE_ROWS <= T_) {
        #pragma unroll
        for (int k = 0; k < 4; ++k) {
            int idx = tid + k * 256;
            if (idx < 825) {
                int c   = idx / 275;
                int rem = idx - c * 275;
                const float4* src = (const float4*)(xn + c * CSLAB + t0 * ROWF);
                ((float4*)(sm + c * SM_CH))[rem] = src[rem];
            }
        }
    } else {
        // last tile (t0=280): clamp halo rows 300,301 -> 299
        for (int idx = tid; idx < C_ * TILE_ROWS * V_; idx += 256) {
            int c   = idx / (TILE_ROWS * V_);
            int rem = idx - c * (TILE_ROWS * V_);
            int r   = rem / V_;
            int v   = rem - r * V_;
            int gt  = t0 + r; if (gt > T_ - 1) gt = T_ - 1;
            ((float2*)(sm + c * SM_CH + r * ROWF))[v] =
                ((const float2*)(xn + c * CSLAB + gt * ROWF))[v];
        }
    }
    __syncthreads();

    if (tid >= 250) return;

    const int rp = tid / 25;                  // row-pair 0..9
    const int k  = tid - rp * 25;             // float4 column 0..24

    // joints j0=2k, j1=2k+1 within the 100-float row-pair segment
    const int j0 = 2 * k;
    const int j1 = 2 * k + 1;
    const int rA = 2 * rp + (j0 >= V_);
    const int vA = j0 - V_ * (j0 >= V_);
    const int rB = 2 * rp + (j1 >= V_);
    const int vB = j1 - V_ * (j1 >= V_);

    const int pvA = __ldg(&conn[vA]);
    const int pvB = __ldg(&conn[vB]);
    const float selA = (t0 + rA < T_ - 2) ? 1.0f : 0.0f;
    const float selB = (t0 + rB < T_ - 2) ? 1.0f : 0.0f;

    float* ob = out + (size_t)n * 18 * CSLAB + (t0 + 2 * rp) * ROWF + 4 * k;

    // ---- phase 1: per-channel compute + immediate stores; keep only bv live ----
    float2 bvA[3], bvB[3];

#pragma unroll
    for (int c = 0; c < C_; ++c) {
        const float* baseA = sm + c * SM_CH + rA * ROWF;
        const float* baseB = sm + c * SM_CH + rB * ROWF;

        float2 aA = ((const float2*)baseA)[vA];
        float2 aB = ((const float2*)baseB)[vB];
        __stcs((float4*)(ob + c * CSLAB), pack4(aA, aB));                      // joint: x

        {
            float2 cA = ((const float2*)baseA)[1];
            float2 cB = ((const float2*)baseB)[1];
            __stcs((float4*)(ob + (c + 3) * CSLAB),
                   make_float4(aA.x - cA.x, aA.y - cA.y,
                               aB.x - cB.x, aB.y - cB.y));                     // x - center
        }
        {
            float2 n1A = ((const float2*)(baseA + ROWF))[vA];
            float2 n1B = ((const float2*)(baseB + ROWF))[vB];
            __stcs((float4*)(ob + (c + 6) * CSLAB),
                   make_float4((n1A.x - aA.x) * selA, (n1A.y - aA.y) * selA,
                               (n1B.x - aB.x) * selB, (n1B.y - aB.y) * selB)); // v1
        }
        {
            float2 n2A = ((const float2*)(baseA + 2 * ROWF))[vA];
            float2 n2B = ((const float2*)(baseB + 2 * ROWF))[vB];
            __stcs((float4*)(ob + (c + 9) * CSLAB),
                   make_float4((n2A.x - aA.x) * selA, (n2A.y - aA.y) * selA,
                               (n2B.x - aB.x) * selB, (n2B.y - aB.y) * selB)); // v2
        }
        {
            float2 pA = ((const float2*)baseA)[pvA];
            float2 pB = ((const float2*)baseB)[pvB];
            bvA[c] = make_float2(aA.x - pA.x, aA.y - pA.y);
            bvB[c] = make_float2(aB.x - pB.x, aB.y - pB.y);
            __stcs((float4*)(ob + (c + 12) * CSLAB), pack4(bvA[c], bvB[c]));   // bone vec
        }
    }

    // ---- phase 2: bone angles ----
    float rAx = 1.0f / (sqrtf(bvA[0].x * bvA[0].x + bvA[1].x * bvA[1].x + bvA[2].x * bvA[2].x) + 1e-4f);
    float rAy = 1.0f / (sqrtf(bvA[0].y * bvA[0].y + bvA[1].y * bvA[1].y + bvA[2].y * bvA[2].y) + 1e-4f);
    float rBx = 1.0f / (sqrtf(bvB[0].x * bvB[0].x + bvB[1].x * bvB[1].x + bvB[2].x * bvB[2].x) + 1e-4f);
    float rBy = 1.0f / (sqrtf(bvB[0].y * bvB[0].y + bvB[1].y * bvB[1].y + bvB[2].y * bvB[2].y) + 1e-4f);

#pragma unroll
    for (int c = 0; c < C_; ++c) {
        __stcs((float4*)(ob + (c + 15) * CSLAB),
               make_float4(acosf(bvA[c].x * rAx), acosf(bvA[c].y * rAy),
                           acosf(bvB[c].x * rBx), acosf(bvB[c].y * rBy)));     // bone angle
    }
}

extern "C" void kernel_launch(void* const* d_in, const int* in_sizes, int n_in,
                              void* d_out, int out_size)
{
    const float* x  = (const float*)d_in[0];
    const int* conn = (const int*)d_in[1];
    float* out      = (float*)d_out;

    const int blocks = N_ * TILES_PER_N;     // 1920
    egcn_preprocess_v6<<<blocks, 256>>>(x, conn, out);
}